// round 10
// baseline (speedup 1.0000x reference)
#include <cuda_runtime.h>

// Problem constants (fixed by reference)
#define N_TOK 16384
#define DIM   1024
#define NPATH 8
#define CAP   4096
#define TPB   256
#define NBLK  (N_TOK / TPB)   // 64 routing blocks
#define G     4               // rows per fill group
#define NGRP  (NPATH * CAP / G)  // 8192 row groups
#define PBLK  592             // 148 SMs x 4 co-resident blocks (persistent grid)

// Scratch (allocation-free: __device__ globals)
__device__ float    g_gate[N_TOK];
__device__ int      g_blockCount[NBLK * NPATH];
__device__ int      g_count[NPATH];          // clamped to CAP
__device__ int      g_inv[NPATH * CAP];      // token index for (path, slot)
__device__ unsigned g_bar1, g_bar2;          // monotonic epoch counters (never reset)

// Grid-wide barrier, replay-safe: each launch adds exactly PBLK arrivals per
// counter; target = next multiple-of-PBLK boundary past my ticket. Low-traffic
// poll: ld.global.cg + nanosleep backoff (avoids 592-way atomic hammering).
__device__ __forceinline__ void grid_barrier(unsigned* bar, int tid) {
    __syncthreads();
    if (tid == 0) {
        __threadfence();                       // release my block's writes
        unsigned ticket = atomicAdd(bar, 1u);
        unsigned target = ((ticket / PBLK) + 1u) * PBLK;
        for (;;) {
            unsigned cur;
            asm volatile("ld.global.cg.u32 %0, [%1];" : "=r"(cur) : "l"(bar));
            if (cur >= target) break;
            __nanosleep(64);
        }
    }
    __syncthreads();
    __threadfence();                           // acquire: others' writes visible
}

// ---------------------------------------------------------------------------
// Single persistent kernel: route -> barrier -> scan+slot -> barrier -> fill.
// ---------------------------------------------------------------------------
__global__ void __launch_bounds__(TPB, 4)
fused_kernel(const float* __restrict__ x,
             const float* __restrict__ scores,
             float* __restrict__ out) {
    int b   = blockIdx.x;
    int tid = threadIdx.x;

    __shared__ int cnt[NPATH];
    __shared__ int s_off[NPATH];
    __shared__ int wcnt[8][NPATH];

    int   best = 0;          // routing state lives in registers across barriers
    float bv   = 0.0f;

    // ---- Phase A: argmax route + per-block histogram (blocks 0..63) ----
    if (b < NBLK) {
        if (tid < NPATH) cnt[tid] = 0;
        __syncthreads();

        int i = b * TPB + tid;
        const float4* s4 = reinterpret_cast<const float4*>(scores);
        float4 a = s4[i * 2 + 0];
        float4 c = s4[i * 2 + 1];
        float v[8] = {a.x, a.y, a.z, a.w, c.x, c.y, c.z, c.w};
        bv = v[0];
#pragma unroll
        for (int k = 1; k < 8; k++)            // first-max wins (jnp.argmax)
            if (v[k] > bv) { bv = v[k]; best = k; }

        g_gate[i] = bv;
        atomicAdd(&cnt[best], 1);
        __syncthreads();
        if (tid < NPATH) g_blockCount[b * NPATH + tid] = cnt[tid];
    }

    grid_barrier(&g_bar1, tid);                // all counts globally visible

    // ---- Phase B: scan + stable slot assignment (blocks 0..63) ----
    if (b < NBLK) {
        if (tid < NPATH) {
            int off = 0, total = 0;
#pragma unroll 8
            for (int bb = 0; bb < NBLK; bb++) {
                int cc = g_blockCount[bb * NPATH + tid];
                if (bb < b) off += cc;
                total += cc;
            }
            s_off[tid] = off;
            if (b == 0) g_count[tid] = total < CAP ? total : CAP;
        }
        if (tid < 8 * NPATH) reinterpret_cast<int*>(wcnt)[tid] = 0;
        __syncthreads();

        int warp = tid >> 5;
        int lane = tid & 31;
        unsigned m     = __match_any_sync(0xffffffffu, best);
        int      wrank = __popc(m & ((1u << lane) - 1u));
        if (wrank == 0) wcnt[warp][best] = __popc(m);
        __syncthreads();

        int base = s_off[best];
#pragma unroll
        for (int w = 0; w < 8; w++)
            if (w < warp) base += wcnt[w][best];

        int i    = b * TPB + tid;
        int slot = base + wrank;
        if (slot < CAP) g_inv[best * CAP + slot] = i;   // overflow -> dropped
    }

    grid_barrier(&g_bar2, tid);                // g_inv / g_count complete

    // ---- Phase C: fill. All 592 blocks loop over 8192 groups of 4 rows. ----
    int t = tid;                               // float4 index within row
    for (int grp = b; grp < NGRP; grp += PBLK) {
        int row0 = grp * G;                    // G divides CAP: no path crossing
        int p    = row0 >> 12;
        int cnt_p = __ldg(&g_count[p]);

        bool act[G];
        int  tok[G];
#pragma unroll
        for (int j = 0; j < G; j++) {
            int row = row0 + j;
            act[j] = (row & (CAP - 1)) < cnt_p;
            tok[j] = act[j] ? __ldg(&g_inv[row]) : 0;
        }

        float gt[G];
#pragma unroll
        for (int j = 0; j < G; j++)
            gt[j] = act[j] ? __ldg(&g_gate[tok[j]]) : 0.0f;

        float4 v[G];
#pragma unroll
        for (int j = 0; j < G; j++) {
            if (act[j]) {
                const float4* x4 =
                    reinterpret_cast<const float4*>(x) + (size_t)tok[j] * (DIM / 4);
                float4 w = __ldg(&x4[t]);
                v[j] = make_float4(w.x * gt[j], w.y * gt[j],
                                   w.z * gt[j], w.w * gt[j]);
            } else {
                v[j] = make_float4(0.f, 0.f, 0.f, 0.f);
            }
        }

#pragma unroll
        for (int j = 0; j < G; j++) {
            float4* o4 = reinterpret_cast<float4*>(out) +
                         (size_t)(row0 + j) * (DIM / 4) + t;
            __stcs(o4, v[j]);                  // evict-first: keep x hot in L2
        }
    }
}

// ---------------------------------------------------------------------------
// Launch: single kernel, single graph node.
// ---------------------------------------------------------------------------
extern "C" void kernel_launch(void* const* d_in, const int* in_sizes, int n_in,
                              void* d_out, int out_size) {
    const float* x      = (const float*)d_in[0];   // [16384, 1024]
    const float* scores = (const float*)d_in[1];   // [16384, 8]
    float*       out    = (float*)d_out;           // [8, 4096, 1024]

    fused_kernel<<<PBLK, TPB>>>(x, scores, out);
}